// round 1
// baseline (speedup 1.0000x reference)
#include <cuda_runtime.h>
#include <math.h>

#define TT 2048
#define HH 1024
#define FF 2816
#define NE 8

// ---------------- scratch (__device__ globals; no allocation allowed) ----------------
__device__ int   g_cnt[NE];
__device__ int   g_tok[NE * TT];
__device__ int   g_kid[NE * TT];
__device__ float g_wgt[NE * TT];
__device__ float g_h[(size_t)NE * TT * FF];    // per-expert compact hidden activations (~184 MB)
__device__ float g_yc[(size_t)TT * 2 * HH];    // per-assignment scaled outputs (~16.8 MB)

// ---------------- kernels ----------------
__global__ void zero_kernel() {
    if (threadIdx.x < NE) g_cnt[threadIdx.x] = 0;
}

// One warp per token: 8 dot products (H=1024), softmax-top2 (renormalized top-2 of a
// softmax == 2-way softmax of the top-2 logits), push assignments to per-expert lists.
__global__ void router_kernel(const float* __restrict__ x, const float* __restrict__ Wgate) {
    int warp = (blockIdx.x * blockDim.x + threadIdx.x) >> 5;
    int lane = threadIdx.x & 31;
    if (warp >= TT) return;
    const float* xt = x + (size_t)warp * HH;
    float acc[NE];
#pragma unroll
    for (int e = 0; e < NE; e++) acc[e] = 0.f;
    for (int k = lane; k < HH; k += 32) {
        float xv = xt[k];
#pragma unroll
        for (int e = 0; e < NE; e++) acc[e] += xv * Wgate[e * HH + k];
    }
#pragma unroll
    for (int off = 16; off > 0; off >>= 1) {
#pragma unroll
        for (int e = 0; e < NE; e++) acc[e] += __shfl_xor_sync(0xffffffffu, acc[e], off);
    }
    if (lane == 0) {
        int i0 = 0; float l0 = acc[0];
#pragma unroll
        for (int e = 1; e < NE; e++) if (acc[e] > l0) { l0 = acc[e]; i0 = e; }
        int i1 = -1; float l1 = -INFINITY;
#pragma unroll
        for (int e = 0; e < NE; e++) if (e != i0 && acc[e] > l1) { l1 = acc[e]; i1 = e; }
        float w0 = 1.f / (1.f + expf(l1 - l0));
        float w1 = 1.f - w0;
        int p0 = atomicAdd(&g_cnt[i0], 1);
        g_tok[i0 * TT + p0] = warp; g_kid[i0 * TT + p0] = 0; g_wgt[i0 * TT + p0] = w0;
        int p1 = atomicAdd(&g_cnt[i1], 1);
        g_tok[i1 * TT + p1] = warp; g_kid[i1 * TT + p1] = 1; g_wgt[i1 * TT + p1] = w1;
    }
}

// Fused gate+up GEMM + SwiGLU. 64x64 tile, 256 threads, 4x4 micro-tile, k-tile 16.
// A = gathered token rows of x [n_e x H]; B = Wg/Wu rows [F x H]; h = silu(g)*u.
#define PAD 68
__global__ __launch_bounds__(256) void gateup_kernel(
    const float* __restrict__ x, const float* __restrict__ Wg, const float* __restrict__ Wu) {
    int e = blockIdx.z;
    int n = g_cnt[e];
    int m0 = blockIdx.y * 64;
    if (m0 >= n) return;
    int n0 = blockIdx.x * 64;

    __shared__ float As[16][PAD];
    __shared__ float Bg[16][PAD];
    __shared__ float Bu[16][PAD];
    __shared__ int stok[64];

    int tid = threadIdx.x;
    if (tid < 64) {
        int r = m0 + tid;
        stok[tid] = g_tok[e * TT + (r < n ? r : n - 1)];
    }
    __syncthreads();

    int lm = tid >> 2;          // 0..63
    int lk = (tid & 3) << 2;    // 0,4,8,12
    const float* xa  = x  + (size_t)stok[lm] * HH + lk;
    const float* wge = Wg + (size_t)e * FF * HH + (size_t)(n0 + lm) * HH + lk;
    const float* wue = Wu + (size_t)e * FF * HH + (size_t)(n0 + lm) * HH + lk;

    int ty = tid >> 4, tx = tid & 15;
    int tm = ty << 2, tn = tx << 2;
    float accg[4][4] = {};
    float accu[4][4] = {};

    for (int k0 = 0; k0 < HH; k0 += 16) {
        float4 av = *(const float4*)(xa + k0);
        float4 gv = *(const float4*)(wge + k0);
        float4 uv = *(const float4*)(wue + k0);
        __syncthreads();
        As[lk + 0][lm] = av.x; As[lk + 1][lm] = av.y; As[lk + 2][lm] = av.z; As[lk + 3][lm] = av.w;
        Bg[lk + 0][lm] = gv.x; Bg[lk + 1][lm] = gv.y; Bg[lk + 2][lm] = gv.z; Bg[lk + 3][lm] = gv.w;
        Bu[lk + 0][lm] = uv.x; Bu[lk + 1][lm] = uv.y; Bu[lk + 2][lm] = uv.z; Bu[lk + 3][lm] = uv.w;
        __syncthreads();
#pragma unroll
        for (int k = 0; k < 16; k++) {
            float a[4], bg[4], bu[4];
#pragma unroll
            for (int i = 0; i < 4; i++) a[i] = As[k][tm + i];
#pragma unroll
            for (int j = 0; j < 4; j++) { bg[j] = Bg[k][tn + j]; bu[j] = Bu[k][tn + j]; }
#pragma unroll
            for (int i = 0; i < 4; i++)
#pragma unroll
                for (int j = 0; j < 4; j++) {
                    accg[i][j] += a[i] * bg[j];
                    accu[i][j] += a[i] * bu[j];
                }
        }
    }

#pragma unroll
    for (int i = 0; i < 4; i++) {
        int r = m0 + tm + i;
        if (r < n) {
            float* hp = g_h + ((size_t)e * TT + r) * FF + n0 + tn;
            float4 o;
            float g0 = accg[i][0], g1 = accg[i][1], g2 = accg[i][2], g3 = accg[i][3];
            o.x = (g0 / (1.f + expf(-g0))) * accu[i][0];
            o.y = (g1 / (1.f + expf(-g1))) * accu[i][1];
            o.z = (g2 / (1.f + expf(-g2))) * accu[i][2];
            o.w = (g3 / (1.f + expf(-g3))) * accu[i][3];
            *(float4*)hp = o;
        }
    }
}

// Down projection: Y = h @ Wd^T, scaled by combine weight, scattered to (token, k) slots.
__global__ __launch_bounds__(256) void down_kernel(const float* __restrict__ Wd) {
    int e = blockIdx.z;
    int n = g_cnt[e];
    int m0 = blockIdx.y * 64;
    if (m0 >= n) return;
    int n0 = blockIdx.x * 64;

    __shared__ float As[16][PAD];
    __shared__ float Bs[16][PAD];

    int tid = threadIdx.x;
    int lm = tid >> 2;
    int lk = (tid & 3) << 2;
    int rA = m0 + lm; if (rA >= n) rA = n - 1;
    const float* ha = g_h + ((size_t)e * TT + rA) * FF + lk;
    const float* wd = Wd + (size_t)e * HH * FF + (size_t)(n0 + lm) * FF + lk;

    int ty = tid >> 4, tx = tid & 15;
    int tm = ty << 2, tn = tx << 2;
    float acc[4][4] = {};

    for (int k0 = 0; k0 < FF; k0 += 16) {
        float4 av = *(const float4*)(ha + k0);
        float4 bv = *(const float4*)(wd + k0);
        __syncthreads();
        As[lk + 0][lm] = av.x; As[lk + 1][lm] = av.y; As[lk + 2][lm] = av.z; As[lk + 3][lm] = av.w;
        Bs[lk + 0][lm] = bv.x; Bs[lk + 1][lm] = bv.y; Bs[lk + 2][lm] = bv.z; Bs[lk + 3][lm] = bv.w;
        __syncthreads();
#pragma unroll
        for (int k = 0; k < 16; k++) {
            float a[4], b[4];
#pragma unroll
            for (int i = 0; i < 4; i++) a[i] = As[k][tm + i];
#pragma unroll
            for (int j = 0; j < 4; j++) b[j] = Bs[k][tn + j];
#pragma unroll
            for (int i = 0; i < 4; i++)
#pragma unroll
                for (int j = 0; j < 4; j++) acc[i][j] += a[i] * b[j];
        }
    }

#pragma unroll
    for (int i = 0; i < 4; i++) {
        int r = m0 + tm + i;
        if (r < n) {
            int t = g_tok[e * TT + r];
            int kk = g_kid[e * TT + r];
            float w = g_wgt[e * TT + r];
            float4 o;
            o.x = acc[i][0] * w; o.y = acc[i][1] * w; o.z = acc[i][2] * w; o.w = acc[i][3] * w;
            *(float4*)(g_yc + ((size_t)(t * 2 + kk)) * HH + n0 + tn) = o;
        }
    }
}

// out[t] = y(t, k=0) + y(t, k=1) — every slot is written every launch, fixed order.
__global__ void combine_kernel(float* __restrict__ out) {
    int i = blockIdx.x * blockDim.x + threadIdx.x;  // over T*H/4
    int t  = i / (HH / 4);
    int h4 = (i % (HH / 4)) * 4;
    float4 a = *(const float4*)(g_yc + ((size_t)t * 2) * HH + h4);
    float4 b = *(const float4*)(g_yc + ((size_t)(t * 2 + 1)) * HH + h4);
    float4 o;
    o.x = a.x + b.x; o.y = a.y + b.y; o.z = a.z + b.z; o.w = a.w + b.w;
    *(float4*)(out + (size_t)t * HH + h4) = o;
}

// ---------------- launch ----------------
extern "C" void kernel_launch(void* const* d_in, const int* in_sizes, int n_in,
                              void* d_out, int out_size) {
    const float* x     = (const float*)d_in[0];
    const float* Wgate = (const float*)d_in[1];
    const float* Wg    = (const float*)d_in[2];
    const float* Wu    = (const float*)d_in[3];
    const float* Wd    = (const float*)d_in[4];
    float* out = (float*)d_out;

    zero_kernel<<<1, 32>>>();
    router_kernel<<<TT / 8, 256>>>(x, Wgate);
    gateup_kernel<<<dim3(FF / 64, TT / 64, NE), 256>>>(x, Wg, Wu);
    down_kernel<<<dim3(HH / 64, TT / 64, NE), 256>>>(Wd);
    combine_kernel<<<(TT * HH / 4) / 256, 256>>>(out);
}

// round 2
// speedup vs baseline: 2.4229x; 2.4229x over previous
#include <cuda_runtime.h>
#include <math.h>
#include <stdint.h>

#define TT 2048
#define HH 1024
#define FF 2816
#define NE 8

// ---------------- scratch ----------------
__device__ int   g_cnt[NE];
__device__ int   g_tok[NE * TT];
__device__ int   g_kid[NE * TT];
__device__ float g_wgt[NE * TT];
__device__ float g_h[(size_t)NE * TT * FF];
__device__ float g_yc[(size_t)TT * 2 * HH];

// ---------------- helpers ----------------
__device__ __forceinline__ float tf32r(float x) {
    uint32_t o;
    asm("cvt.rna.tf32.f32 %0, %1;" : "=r"(o) : "f"(x));
    return __uint_as_float(o);
}

__device__ __forceinline__ void mma_tf32(float* d, const float* a, const float* b) {
    asm volatile(
        "mma.sync.aligned.m16n8k8.row.col.f32.tf32.tf32.f32 "
        "{%0,%1,%2,%3}, {%4,%5,%6,%7}, {%8,%9}, {%0,%1,%2,%3};\n"
        : "+f"(d[0]), "+f"(d[1]), "+f"(d[2]), "+f"(d[3])
        : "r"(__float_as_uint(a[0])), "r"(__float_as_uint(a[1])),
          "r"(__float_as_uint(a[2])), "r"(__float_as_uint(a[3])),
          "r"(__float_as_uint(b[0])), "r"(__float_as_uint(b[1])));
}

// ---------------- setup kernels ----------------
__global__ void zero_kernel() {
    if (threadIdx.x < NE) g_cnt[threadIdx.x] = 0;
}

__global__ void router_kernel(const float* __restrict__ x, const float* __restrict__ Wgate) {
    int warp = (blockIdx.x * blockDim.x + threadIdx.x) >> 5;
    int lane = threadIdx.x & 31;
    if (warp >= TT) return;
    const float* xt = x + (size_t)warp * HH;
    float acc[NE];
#pragma unroll
    for (int e = 0; e < NE; e++) acc[e] = 0.f;
    for (int k = lane; k < HH; k += 32) {
        float xv = xt[k];
#pragma unroll
        for (int e = 0; e < NE; e++) acc[e] += xv * Wgate[e * HH + k];
    }
#pragma unroll
    for (int off = 16; off > 0; off >>= 1) {
#pragma unroll
        for (int e = 0; e < NE; e++) acc[e] += __shfl_xor_sync(0xffffffffu, acc[e], off);
    }
    if (lane == 0) {
        int i0 = 0; float l0 = acc[0];
#pragma unroll
        for (int e = 1; e < NE; e++) if (acc[e] > l0) { l0 = acc[e]; i0 = e; }
        int i1 = -1; float l1 = -INFINITY;
#pragma unroll
        for (int e = 0; e < NE; e++) if (e != i0 && acc[e] > l1) { l1 = acc[e]; i1 = e; }
        float w0 = 1.f / (1.f + expf(l1 - l0));
        float w1 = 1.f - w0;
        int p0 = atomicAdd(&g_cnt[i0], 1);
        g_tok[i0 * TT + p0] = warp; g_kid[i0 * TT + p0] = 0; g_wgt[i0 * TT + p0] = w0;
        int p1 = atomicAdd(&g_cnt[i1], 1);
        g_tok[i1 * TT + p1] = warp; g_kid[i1 * TT + p1] = 1; g_wgt[i1 * TT + p1] = w1;
    }
}

// ---------------- gate+up GEMM (tf32 mma.sync) ----------------
// Block: 128 tokens x 64 f-cols (computes both g and u), 512 threads (16 warps 4x4),
// warp tile 32x16 per gemm, BK=32 (4 ksteps of m16n8k8).
#define SKA 36
__global__ __launch_bounds__(512) void gateup_mma(
    const float* __restrict__ x, const float* __restrict__ Wg, const float* __restrict__ Wu) {
    int e  = blockIdx.z;
    int n  = g_cnt[e];
    int m0 = blockIdx.x * 128;
    if (m0 >= n) return;
    int n0 = blockIdx.y * 64;

    __shared__ float As[128][SKA];
    __shared__ float Bg[64][SKA];
    __shared__ float Bu[64][SKA];
    __shared__ int   stok[128];

    int tid  = threadIdx.x;
    int lane = tid & 31;
    int wid  = tid >> 5;
    int wm   = wid >> 2;  // 0..3 -> rows wm*32
    int wn   = wid & 3;   // 0..3 -> cols wn*16

    if (tid < 128) {
        int r = m0 + tid;
        stok[tid] = g_tok[e * TT + (r < n ? r : n - 1)];
    }
    __syncthreads();

    const float* wg_base = Wg + (size_t)e * FF * HH;
    const float* wu_base = Wu + (size_t)e * FF * HH;

    float accg[2][2][4] = {};
    float accu[2][2][4] = {};

    int ar0 = (tid) >> 3;            // A row for load pass 0 (tid 0..511 -> row 0..63)
    int aq  = tid & 7;               // float4 index in row
    int br  = tid >> 3;              // B row 0..63
    int bq  = tid & 7;

    for (int k0 = 0; k0 < HH; k0 += 32) {
        __syncthreads();
        // A: 128 rows x 32 -> 1024 float4, 2 per thread
#pragma unroll
        for (int i = 0; i < 2; i++) {
            int f = tid + i * 512;
            int r = f >> 3, q = f & 7;
            float4 v = *(const float4*)(x + (size_t)stok[r] * HH + k0 + q * 4);
            As[r][q * 4 + 0] = tf32r(v.x); As[r][q * 4 + 1] = tf32r(v.y);
            As[r][q * 4 + 2] = tf32r(v.z); As[r][q * 4 + 3] = tf32r(v.w);
        }
        // Bg / Bu: 64 rows x 32 each -> 512 float4 each, 1 per thread
        {
            float4 v = *(const float4*)(wg_base + (size_t)(n0 + br) * HH + k0 + bq * 4);
            Bg[br][bq * 4 + 0] = tf32r(v.x); Bg[br][bq * 4 + 1] = tf32r(v.y);
            Bg[br][bq * 4 + 2] = tf32r(v.z); Bg[br][bq * 4 + 3] = tf32r(v.w);
            float4 u = *(const float4*)(wu_base + (size_t)(n0 + br) * HH + k0 + bq * 4);
            Bu[br][bq * 4 + 0] = tf32r(u.x); Bu[br][bq * 4 + 1] = tf32r(u.y);
            Bu[br][bq * 4 + 2] = tf32r(u.z); Bu[br][bq * 4 + 3] = tf32r(u.w);
        }
        __syncthreads();

#pragma unroll
        for (int ks = 0; ks < 4; ks++) {
            int k = ks * 8;
            float afr[2][4];
#pragma unroll
            for (int i2 = 0; i2 < 2; i2++) {
                int rb = wm * 32 + i2 * 16;
                afr[i2][0] = As[rb + (lane >> 2)][k + (lane & 3)];
                afr[i2][1] = As[rb + 8 + (lane >> 2)][k + (lane & 3)];
                afr[i2][2] = As[rb + (lane >> 2)][k + 4 + (lane & 3)];
                afr[i2][3] = As[rb + 8 + (lane >> 2)][k + 4 + (lane & 3)];
            }
#pragma unroll
            for (int j2 = 0; j2 < 2; j2++) {
                int cb = wn * 16 + j2 * 8;
                float bg[2], bu[2];
                bg[0] = Bg[cb + (lane >> 2)][k + (lane & 3)];
                bg[1] = Bg[cb + (lane >> 2)][k + 4 + (lane & 3)];
                bu[0] = Bu[cb + (lane >> 2)][k + (lane & 3)];
                bu[1] = Bu[cb + (lane >> 2)][k + 4 + (lane & 3)];
#pragma unroll
                for (int i2 = 0; i2 < 2; i2++) {
                    mma_tf32(accg[i2][j2], afr[i2], bg);
                    mma_tf32(accu[i2][j2], afr[i2], bu);
                }
            }
        }
    }

    // epilogue: SwiGLU, store to g_h
#pragma unroll
    for (int i2 = 0; i2 < 2; i2++) {
#pragma unroll
        for (int j2 = 0; j2 < 2; j2++) {
            int col = n0 + wn * 16 + j2 * 8 + (lane & 3) * 2;
            int r0  = m0 + wm * 32 + i2 * 16 + (lane >> 2);
            if (r0 < n) {
                float g0 = accg[i2][j2][0], g1 = accg[i2][j2][1];
                float2 o;
                o.x = (g0 / (1.f + expf(-g0))) * accu[i2][j2][0];
                o.y = (g1 / (1.f + expf(-g1))) * accu[i2][j2][1];
                *(float2*)(g_h + ((size_t)e * TT + r0) * FF + col) = o;
            }
            int r1 = r0 + 8;
            if (r1 < n) {
                float g2 = accg[i2][j2][2], g3 = accg[i2][j2][3];
                float2 o;
                o.x = (g2 / (1.f + expf(-g2))) * accu[i2][j2][2];
                o.y = (g3 / (1.f + expf(-g3))) * accu[i2][j2][3];
                *(float2*)(g_h + ((size_t)e * TT + r1) * FF + col) = o;
            }
        }
    }
}

// ---------------- down GEMM (tf32 mma.sync) ----------------
// Block: 128 rows x 64 h-cols, 512 threads, warp tile 32x16, K=FF.
__global__ __launch_bounds__(512) void down_mma(const float* __restrict__ Wd) {
    int e  = blockIdx.z;
    int n  = g_cnt[e];
    int m0 = blockIdx.x * 128;
    if (m0 >= n) return;
    int n0 = blockIdx.y * 64;

    __shared__ float As[128][SKA];
    __shared__ float Bs[64][SKA];

    int tid  = threadIdx.x;
    int lane = tid & 31;
    int wid  = tid >> 5;
    int wm   = wid >> 2;
    int wn   = wid & 3;

    const float* wd_base = Wd + (size_t)e * HH * FF;
    const float* h_base  = g_h + (size_t)e * TT * FF;

    float acc[2][2][4] = {};

    int br = tid >> 3;
    int bq = tid & 7;

    for (int k0 = 0; k0 < FF; k0 += 32) {
        __syncthreads();
#pragma unroll
        for (int i = 0; i < 2; i++) {
            int f = tid + i * 512;
            int r = f >> 3, q = f & 7;
            int rc = m0 + r; if (rc >= n) rc = n - 1;
            float4 v = *(const float4*)(h_base + (size_t)rc * FF + k0 + q * 4);
            As[r][q * 4 + 0] = tf32r(v.x); As[r][q * 4 + 1] = tf32r(v.y);
            As[r][q * 4 + 2] = tf32r(v.z); As[r][q * 4 + 3] = tf32r(v.w);
        }
        {
            float4 v = *(const float4*)(wd_base + (size_t)(n0 + br) * FF + k0 + bq * 4);
            Bs[br][bq * 4 + 0] = tf32r(v.x); Bs[br][bq * 4 + 1] = tf32r(v.y);
            Bs[br][bq * 4 + 2] = tf32r(v.z); Bs[br][bq * 4 + 3] = tf32r(v.w);
        }
        __syncthreads();

#pragma unroll
        for (int ks = 0; ks < 4; ks++) {
            int k = ks * 8;
            float afr[2][4];
#pragma unroll
            for (int i2 = 0; i2 < 2; i2++) {
                int rb = wm * 32 + i2 * 16;
                afr[i2][0] = As[rb + (lane >> 2)][k + (lane & 3)];
                afr[i2][1] = As[rb + 8 + (lane >> 2)][k + (lane & 3)];
                afr[i2][2] = As[rb + (lane >> 2)][k + 4 + (lane & 3)];
                afr[i2][3] = As[rb + 8 + (lane >> 2)][k + 4 + (lane & 3)];
            }
#pragma unroll
            for (int j2 = 0; j2 < 2; j2++) {
                int cb = wn * 16 + j2 * 8;
                float bf[2];
                bf[0] = Bs[cb + (lane >> 2)][k + (lane & 3)];
                bf[1] = Bs[cb + (lane >> 2)][k + 4 + (lane & 3)];
#pragma unroll
                for (int i2 = 0; i2 < 2; i2++) mma_tf32(acc[i2][j2], afr[i2], bf);
            }
        }
    }

#pragma unroll
    for (int i2 = 0; i2 < 2; i2++) {
#pragma unroll
        for (int j2 = 0; j2 < 2; j2++) {
            int col = n0 + wn * 16 + j2 * 8 + (lane & 3) * 2;
            int r0  = m0 + wm * 32 + i2 * 16 + (lane >> 2);
            if (r0 < n) {
                int t = g_tok[e * TT + r0], kk = g_kid[e * TT + r0];
                float w = g_wgt[e * TT + r0];
                float2 o; o.x = acc[i2][j2][0] * w; o.y = acc[i2][j2][1] * w;
                *(float2*)(g_yc + ((size_t)(t * 2 + kk)) * HH + col) = o;
            }
            int r1 = r0 + 8;
            if (r1 < n) {
                int t = g_tok[e * TT + r1], kk = g_kid[e * TT + r1];
                float w = g_wgt[e * TT + r1];
                float2 o; o.x = acc[i2][j2][2] * w; o.y = acc[i2][j2][3] * w;
                *(float2*)(g_yc + ((size_t)(t * 2 + kk)) * HH + col) = o;
            }
        }
    }
}

__global__ void combine_kernel(float* __restrict__ out) {
    int i = blockIdx.x * blockDim.x + threadIdx.x;
    int t  = i / (HH / 4);
    int h4 = (i % (HH / 4)) * 4;
    float4 a = *(const float4*)(g_yc + ((size_t)t * 2) * HH + h4);
    float4 b = *(const float4*)(g_yc + ((size_t)(t * 2 + 1)) * HH + h4);
    float4 o;
    o.x = a.x + b.x; o.y = a.y + b.y; o.z = a.z + b.z; o.w = a.w + b.w;
    *(float4*)(out + (size_t)t * HH + h4) = o;
}

// ---------------- launch ----------------
extern "C" void kernel_launch(void* const* d_in, const int* in_sizes, int n_in,
                              void* d_out, int out_size) {
    const float* x     = (const float*)d_in[0];
    const float* Wgate = (const float*)d_in[1];
    const float* Wg    = (const float*)d_in[2];
    const float* Wu    = (const float*)d_in[3];
    const float* Wd    = (const float*)d_in[4];
    float* out = (float*)d_out;

    zero_kernel<<<1, 32>>>();
    router_kernel<<<TT / 8, 256>>>(x, Wgate);
    // x = m-tile (fastest) so blocks sharing a weight tile co-schedule -> L2 reuse
    gateup_mma<<<dim3(TT / 128, FF / 64, NE), 512>>>(x, Wg, Wu);
    down_mma<<<dim3(TT / 128, HH / 64, NE), 512>>>(Wd);
    combine_kernel<<<(TT * HH / 4) / 256, 256>>>(out);
}

// round 4
// speedup vs baseline: 4.3814x; 1.8083x over previous
#include <cuda_runtime.h>
#include <cuda_fp16.h>
#include <math.h>
#include <stdint.h>

#define TT 2048
#define HH 1024
#define FF 2816
#define NE 8
#define BM 128
#define BN 64
#define BKH 32
#define ASTR 40   // halves per smem row (32 + 8 pad) -> conflict-free ldmatrix

// ---------------- scratch ----------------
__device__ int    g_cnt[NE];
__device__ int    g_tok[NE * TT];
__device__ int    g_kid[NE * TT];
__device__ float  g_wgt[NE * TT];
__device__ __half g_xh[(size_t)NE * TT * HH];   // gathered activations, fp16 (32MB)
__device__ __half g_hh[(size_t)NE * TT * FF];   // swiglu output, fp16 (92MB)
__device__ float  g_yc[(size_t)TT * 2 * HH];

// ---------------- helpers ----------------
__device__ __forceinline__ uint32_t smem_u32(const void* p) {
    uint32_t a;
    asm("{ .reg .u64 t; cvta.to.shared.u64 t, %1; cvt.u32.u64 %0, t; }" : "=r"(a) : "l"(p));
    return a;
}
__device__ __forceinline__ void ldsm4(uint32_t* r, uint32_t a) {
    asm volatile("ldmatrix.sync.aligned.m8n8.x4.shared.b16 {%0,%1,%2,%3}, [%4];"
        : "=r"(r[0]), "=r"(r[1]), "=r"(r[2]), "=r"(r[3]) : "r"(a));
}
__device__ __forceinline__ void mma16816(float* d, const uint32_t* a, const uint32_t* b) {
    asm volatile("mma.sync.aligned.m16n8k16.row.col.f32.f16.f16.f32 "
        "{%0,%1,%2,%3}, {%4,%5,%6,%7}, {%8,%9}, {%0,%1,%2,%3};"
        : "+f"(d[0]), "+f"(d[1]), "+f"(d[2]), "+f"(d[3])
        : "r"(a[0]), "r"(a[1]), "r"(a[2]), "r"(a[3]), "r"(b[0]), "r"(b[1]));
}
__device__ __forceinline__ void cp16(uint32_t d, const void* s) {
    asm volatile("cp.async.ca.shared.global [%0], [%1], 16;" :: "r"(d), "l"(s));
}
#define CP_COMMIT() asm volatile("cp.async.commit_group;" ::: "memory")
#define CP_WAIT()   asm volatile("cp.async.wait_group 0;" ::: "memory")

__device__ __forceinline__ void sts8(__half* dst, float4 a, float4 b) {
    __half2 h0 = __floats2half2_rn(a.x, a.y);
    __half2 h1 = __floats2half2_rn(a.z, a.w);
    __half2 h2 = __floats2half2_rn(b.x, b.y);
    __half2 h3 = __floats2half2_rn(b.z, b.w);
    uint4 v;
    v.x = *(uint32_t*)&h0; v.y = *(uint32_t*)&h1;
    v.z = *(uint32_t*)&h2; v.w = *(uint32_t*)&h3;
    *(uint4*)dst = v;
}

// ---------------- setup kernels ----------------
__global__ void zero_kernel() {
    if (threadIdx.x < NE) g_cnt[threadIdx.x] = 0;
}

__global__ void router_kernel(const float* __restrict__ x, const float* __restrict__ Wgate) {
    int warp = (blockIdx.x * blockDim.x + threadIdx.x) >> 5;
    int lane = threadIdx.x & 31;
    if (warp >= TT) return;
    const float* xt = x + (size_t)warp * HH;
    float acc[NE];
#pragma unroll
    for (int e = 0; e < NE; e++) acc[e] = 0.f;
    for (int k = lane; k < HH; k += 32) {
        float xv = xt[k];
#pragma unroll
        for (int e = 0; e < NE; e++) acc[e] += xv * Wgate[e * HH + k];
    }
#pragma unroll
    for (int off = 16; off > 0; off >>= 1) {
#pragma unroll
        for (int e = 0; e < NE; e++) acc[e] += __shfl_xor_sync(0xffffffffu, acc[e], off);
    }
    if (lane == 0) {
        int i0 = 0; float l0 = acc[0];
#pragma unroll
        for (int e = 1; e < NE; e++) if (acc[e] > l0) { l0 = acc[e]; i0 = e; }
        int i1 = -1; float l1 = -INFINITY;
#pragma unroll
        for (int e = 0; e < NE; e++) if (e != i0 && acc[e] > l1) { l1 = acc[e]; i1 = e; }
        float w0 = 1.f / (1.f + expf(l1 - l0));
        float w1 = 1.f - w0;
        int p0 = atomicAdd(&g_cnt[i0], 1);
        g_tok[i0 * TT + p0] = warp; g_kid[i0 * TT + p0] = 0; g_wgt[i0 * TT + p0] = w0;
        int p1 = atomicAdd(&g_cnt[i1], 1);
        g_tok[i1 * TT + p1] = warp; g_kid[i1 * TT + p1] = 1; g_wgt[i1 * TT + p1] = w1;
    }
}

// gather x rows into per-expert compact fp16 layout (one warp per slot)
__global__ void gather_kernel(const float* __restrict__ x) {
    int slot = blockIdx.x * 8 + (threadIdx.x >> 5);
    int lane = threadIdx.x & 31;
    int e = slot / TT, r = slot % TT;
    if (r >= g_cnt[e]) return;
    int t = g_tok[e * TT + r];
    const float4* src = (const float4*)(x + (size_t)t * HH);
    __half2* dst = (__half2*)(g_xh + (size_t)slot * HH);
#pragma unroll
    for (int q = 0; q < HH / 128; q++) {
        float4 v = src[lane + q * 32];
        dst[(lane + q * 32) * 2 + 0] = __floats2half2_rn(v.x, v.y);
        dst[(lane + q * 32) * 2 + 1] = __floats2half2_rn(v.z, v.w);
    }
}

// ---------------- gate+up: fp16 mma.m16n8k16, ldmatrix, cp.async pipeline ----------------
// Block 128x64, 256 threads, warps 2x4, warp tile 64x16 (per operand).
__global__ __launch_bounds__(256) void gateup_hmma(const float* __restrict__ Wg,
                                                   const float* __restrict__ Wu) {
    const int STG = BM * ASTR + 2 * BN * ASTR;  // halves per stage (A, Bg, Bu)
    __shared__ __half sh[2 * STG];

    int e = blockIdx.z, n = g_cnt[e];
    int m0 = blockIdx.x * BM;
    if (m0 >= n) return;
    int n0 = blockIdx.y * BN;

    int tid = threadIdx.x, lane = tid & 31, wid = tid >> 5;
    int wm = wid >> 2, wn = wid & 3;
    uint32_t sb = smem_u32(sh);

    const __half* xab = g_xh + (size_t)e * TT * HH;
    const float*  wgb = Wg + (size_t)e * FF * HH;
    const float*  wub = Wu + (size_t)e * FF * HH;

    // A cp.async mapping: 512 16B chunks, 2 per thread
    const __half* asrc[2]; uint32_t adst[2];
#pragma unroll
    for (int i = 0; i < 2; i++) {
        int ch = tid + i * 256, r = ch >> 2, c = ch & 3;
        int rc = m0 + r; if (rc >= n) rc = n - 1;
        asrc[i] = xab + (size_t)rc * HH + c * 8;
        adst[i] = sb + (r * ASTR + c * 8) * 2;
    }
    // B: row tid>>2 (0..63), chunk tid&3 (8 floats)
    int brow = tid >> 2, bc = tid & 3;
    const float* gsrc = wgb + (size_t)(n0 + brow) * HH + bc * 8;
    const float* usrc = wub + (size_t)(n0 + brow) * HH + bc * 8;
    __half* bgst = sh + BM * ASTR + brow * ASTR + bc * 8;
    __half* bust = bgst + BN * ASTR;

    // fragment base addresses (stage 0)
    int seg = lane >> 3, li = lane & 7;
    uint32_t aA[4], aG, aU;
#pragma unroll
    for (int i = 0; i < 4; i++) {
        int row = wm * 64 + i * 16 + li + (seg & 1) * 8;
        aA[i] = sb + (row * ASTR + (seg >> 1) * 8) * 2;
    }
    {
        int row = wn * 16 + li + (seg >> 1) * 8;
        aG = sb + (BM * ASTR + row * ASTR + (seg & 1) * 8) * 2;
        aU = aG + BN * ASTR * 2;
    }

    float accg[4][2][4] = {}, accu[4][2][4] = {};

    // prologue: stage 0
    cp16(adst[0], asrc[0]); cp16(adst[1], asrc[1]); CP_COMMIT();
    float4 vg0 = *(const float4*)gsrc, vg1 = *(const float4*)(gsrc + 4);
    float4 vu0 = *(const float4*)usrc, vu1 = *(const float4*)(usrc + 4);
    sts8(bgst, vg0, vg1); sts8(bust, vu0, vu1);
    CP_WAIT();
    __syncthreads();

    const int KT = HH / BKH;  // 32
    for (int kt = 0; kt < KT; kt++) {
        int cur = kt & 1;
        uint32_t so = (uint32_t)(cur * STG * 2);
        bool more = (kt + 1 < KT);
        if (more) {
            int k0 = (kt + 1) * BKH;
            uint32_t po = (uint32_t)((cur ^ 1) * STG * 2);
            cp16(adst[0] + po, asrc[0] + k0);
            cp16(adst[1] + po, asrc[1] + k0);
            CP_COMMIT();
            vg0 = *(const float4*)(gsrc + k0); vg1 = *(const float4*)(gsrc + k0 + 4);
            vu0 = *(const float4*)(usrc + k0); vu1 = *(const float4*)(usrc + k0 + 4);
        }
#pragma unroll
        for (int ks = 0; ks < 2; ks++) {
            uint32_t af[4][4], bg[4], bu[4];
            ldsm4(bg, aG + so + ks * 32);
            ldsm4(bu, aU + so + ks * 32);
#pragma unroll
            for (int i = 0; i < 4; i++) ldsm4(af[i], aA[i] + so + ks * 32);
#pragma unroll
            for (int i = 0; i < 4; i++)
#pragma unroll
                for (int j = 0; j < 2; j++) {
                    mma16816(accg[i][j], af[i], &bg[j * 2]);
                    mma16816(accu[i][j], af[i], &bu[j * 2]);
                }
        }
        if (more) {
            __half* bo = bgst + (cur ^ 1) * STG;
            sts8(bo, vg0, vg1);
            sts8(bo + BN * ASTR, vu0, vu1);
            CP_WAIT();
        }
        __syncthreads();
    }

    // epilogue: SwiGLU -> fp16 g_hh
#pragma unroll
    for (int i = 0; i < 4; i++) {
        int row0 = m0 + wm * 64 + i * 16 + (lane >> 2);
        int row1 = row0 + 8;
#pragma unroll
        for (int j = 0; j < 2; j++) {
            int col = n0 + wn * 16 + j * 8 + (lane & 3) * 2;
            if (row0 < n) {
                float a0 = accg[i][j][0], a1 = accg[i][j][1];
                float h0 = (a0 / (1.f + expf(-a0))) * accu[i][j][0];
                float h1 = (a1 / (1.f + expf(-a1))) * accu[i][j][1];
                *(__half2*)(g_hh + ((size_t)e * TT + row0) * FF + col) = __floats2half2_rn(h0, h1);
            }
            if (row1 < n) {
                float a2 = accg[i][j][2], a3 = accg[i][j][3];
                float h2 = (a2 / (1.f + expf(-a2))) * accu[i][j][2];
                float h3 = (a3 / (1.f + expf(-a3))) * accu[i][j][3];
                *(__half2*)(g_hh + ((size_t)e * TT + row1) * FF + col) = __floats2half2_rn(h2, h3);
            }
        }
    }
}

// ---------------- down: fp16 mma, K=FF ----------------
__global__ __launch_bounds__(256) void down_hmma(const float* __restrict__ Wd) {
    const int STG = BM * ASTR + BN * ASTR;  // A + B
    __shared__ __half sh[2 * STG];

    int e = blockIdx.z, n = g_cnt[e];
    int m0 = blockIdx.x * BM;
    if (m0 >= n) return;
    int n0 = blockIdx.y * BN;

    int tid = threadIdx.x, lane = tid & 31, wid = tid >> 5;
    int wm = wid >> 2, wn = wid & 3;
    uint32_t sb = smem_u32(sh);

    const __half* hab = g_hh + (size_t)e * TT * FF;
    const float*  wdb = Wd + (size_t)e * HH * FF;

    const __half* asrc[2]; uint32_t adst[2];
#pragma unroll
    for (int i = 0; i < 2; i++) {
        int ch = tid + i * 256, r = ch >> 2, c = ch & 3;
        int rc = m0 + r; if (rc >= n) rc = n - 1;
        asrc[i] = hab + (size_t)rc * FF + c * 8;
        adst[i] = sb + (r * ASTR + c * 8) * 2;
    }
    int brow = tid >> 2, bc = tid & 3;
    const float* bsrc = wdb + (size_t)(n0 + brow) * FF + bc * 8;
    __half* bst = sh + BM * ASTR + brow * ASTR + bc * 8;

    int seg = lane >> 3, li = lane & 7;
    uint32_t aA[4], aB;
#pragma unroll
    for (int i = 0; i < 4; i++) {
        int row = wm * 64 + i * 16 + li + (seg & 1) * 8;
        aA[i] = sb + (row * ASTR + (seg >> 1) * 8) * 2;
    }
    {
        int row = wn * 16 + li + (seg >> 1) * 8;
        aB = sb + (BM * ASTR + row * ASTR + (seg & 1) * 8) * 2;
    }

    float acc[4][2][4] = {};

    cp16(adst[0], asrc[0]); cp16(adst[1], asrc[1]); CP_COMMIT();
    float4 vb0 = *(const float4*)bsrc, vb1 = *(const float4*)(bsrc + 4);
    sts8(bst, vb0, vb1);
    CP_WAIT();
    __syncthreads();

    const int KT = FF / BKH;  // 88
    for (int kt = 0; kt < KT; kt++) {
        int cur = kt & 1;
        uint32_t so = (uint32_t)(cur * STG * 2);
        bool more = (kt + 1 < KT);
        if (more) {
            int k0 = (kt + 1) * BKH;
            uint32_t po = (uint32_t)((cur ^ 1) * STG * 2);
            cp16(adst[0] + po, asrc[0] + k0);
            cp16(adst[1] + po, asrc[1] + k0);
            CP_COMMIT();
            vb0 = *(const float4*)(bsrc + k0); vb1 = *(const float4*)(bsrc + k0 + 4);
        }
#pragma unroll
        for (int ks = 0; ks < 2; ks++) {
            uint32_t af[4][4], bf[4];
            ldsm4(bf, aB + so + ks * 32);
#pragma unroll
            for (int i = 0; i < 4; i++) ldsm4(af[i], aA[i] + so + ks * 32);
#pragma unroll
            for (int i = 0; i < 4; i++)
#pragma unroll
                for (int j = 0; j < 2; j++) mma16816(acc[i][j], af[i], &bf[j * 2]);
        }
        if (more) {
            sts8(bst + (cur ^ 1) * STG, vb0, vb1);
            CP_WAIT();
        }
        __syncthreads();
    }

    // epilogue: scale by combine weight, scatter fp32
#pragma unroll
    for (int i = 0; i < 4; i++) {
        int row0 = m0 + wm * 64 + i * 16 + (lane >> 2);
        int row1 = row0 + 8;
        bool v0 = row0 < n, v1 = row1 < n;
        int t0 = 0, kk0 = 0; float w0 = 0.f;
        if (v0) { t0 = g_tok[e * TT + row0]; kk0 = g_kid[e * TT + row0]; w0 = g_wgt[e * TT + row0]; }
        int t1 = 0, kk1 = 0; float w1 = 0.f;
        if (v1) { t1 = g_tok[e * TT + row1]; kk1 = g_kid[e * TT + row1]; w1 = g_wgt[e * TT + row1]; }
#pragma unroll
        for (int j = 0; j < 2; j++) {
            int col = n0 + wn * 16 + j * 8 + (lane & 3) * 2;
            if (v0) {
                float2 o; o.x = acc[i][j][0] * w0; o.y = acc[i][j][1] * w0;
                *(float2*)(g_yc + ((size_t)(t0 * 2 + kk0)) * HH + col) = o;
            }
            if (v1) {
                float2 o; o.x = acc[i][j][2] * w1; o.y = acc[i][j][3] * w1;
                *(float2*)(g_yc + ((size_t)(t1 * 2 + kk1)) * HH + col) = o;
            }
        }
    }
}

__global__ void combine_kernel(float* __restrict__ out) {
    int i = blockIdx.x * blockDim.x + threadIdx.x;
    int t  = i / (HH / 4);
    int h4 = (i % (HH / 4)) * 4;
    float4 a = *(const float4*)(g_yc + ((size_t)t * 2) * HH + h4);
    float4 b = *(const float4*)(g_yc + ((size_t)(t * 2 + 1)) * HH + h4);
    float4 o;
    o.x = a.x + b.x; o.y = a.y + b.y; o.z = a.z + b.z; o.w = a.w + b.w;
    *(float4*)(out + (size_t)t * HH + h4) = o;
}

// ---------------- launch ----------------
extern "C" void kernel_launch(void* const* d_in, const int* in_sizes, int n_in,
                              void* d_out, int out_size) {
    const float* x     = (const float*)d_in[0];
    const float* Wgate = (const float*)d_in[1];
    const float* Wg    = (const float*)d_in[2];
    const float* Wu    = (const float*)d_in[3];
    const float* Wd    = (const float*)d_in[4];
    float* out = (float*)d_out;

    zero_kernel<<<1, 32>>>();
    router_kernel<<<TT / 8, 256>>>(x, Wgate);
    gather_kernel<<<NE * TT / 8, 256>>>(x);
    gateup_hmma<<<dim3(TT / 128, FF / 64, NE), 256>>>(Wg, Wu);
    down_hmma<<<dim3(TT / 128, HH / 64, NE), 256>>>(Wd);
    combine_kernel<<<(TT * HH / 4) / 256, 256>>>(out);
}

// round 5
// speedup vs baseline: 4.4083x; 1.0061x over previous
#include <cuda_runtime.h>
#include <cuda_fp16.h>
#include <math.h>
#include <stdint.h>

#define TT 2048
#define HH 1024
#define FF 2816
#define NE 8
#define BM 128
#define BN 64
#define BKH 32
#define ASTR 40   // halves per smem row (32 + 8 pad) -> conflict-free ldmatrix

// ---------------- scratch ----------------
__device__ int    g_cnt[NE];
__device__ int    g_tok[NE * TT];
__device__ int    g_kid[NE * TT];
__device__ float  g_wgt[NE * TT];
__device__ __half g_xh[(size_t)NE * TT * HH];   // gathered activations, fp16 (32MB)
__device__ __half g_hh[(size_t)NE * TT * FF];   // swiglu output, fp16 (92MB)
__device__ float  g_yc[(size_t)TT * 2 * HH];

// ---------------- helpers ----------------
__device__ __forceinline__ uint32_t smem_u32(const void* p) {
    uint32_t a;
    asm("{ .reg .u64 t; cvta.to.shared.u64 t, %1; cvt.u32.u64 %0, t; }" : "=r"(a) : "l"(p));
    return a;
}
__device__ __forceinline__ void ldsm4(uint32_t* r, uint32_t a) {
    asm volatile("ldmatrix.sync.aligned.m8n8.x4.shared.b16 {%0,%1,%2,%3}, [%4];"
        : "=r"(r[0]), "=r"(r[1]), "=r"(r[2]), "=r"(r[3]) : "r"(a));
}
__device__ __forceinline__ void mma16816(float* d, const uint32_t* a, const uint32_t* b) {
    asm volatile("mma.sync.aligned.m16n8k16.row.col.f32.f16.f16.f32 "
        "{%0,%1,%2,%3}, {%4,%5,%6,%7}, {%8,%9}, {%0,%1,%2,%3};"
        : "+f"(d[0]), "+f"(d[1]), "+f"(d[2]), "+f"(d[3])
        : "r"(a[0]), "r"(a[1]), "r"(a[2]), "r"(a[3]), "r"(b[0]), "r"(b[1]));
}
__device__ __forceinline__ void cp16(uint32_t d, const void* s) {
    asm volatile("cp.async.ca.shared.global [%0], [%1], 16;" :: "r"(d), "l"(s));
}
#define CP_COMMIT() asm volatile("cp.async.commit_group;" ::: "memory")
#define CP_WAIT()   asm volatile("cp.async.wait_group 0;" ::: "memory")

__device__ __forceinline__ void sts8(__half* dst, float4 a, float4 b) {
    __half2 h0 = __floats2half2_rn(a.x, a.y);
    __half2 h1 = __floats2half2_rn(a.z, a.w);
    __half2 h2 = __floats2half2_rn(b.x, b.y);
    __half2 h3 = __floats2half2_rn(b.z, b.w);
    uint4 v;
    v.x = *(uint32_t*)&h0; v.y = *(uint32_t*)&h1;
    v.z = *(uint32_t*)&h2; v.w = *(uint32_t*)&h3;
    *(uint4*)dst = v;
}

// ---------------- setup kernels ----------------
__global__ void zero_kernel() {
    if (threadIdx.x < NE) g_cnt[threadIdx.x] = 0;
}

__global__ void router_kernel(const float* __restrict__ x, const float* __restrict__ Wgate) {
    int warp = (blockIdx.x * blockDim.x + threadIdx.x) >> 5;
    int lane = threadIdx.x & 31;
    if (warp >= TT) return;
    const float* xt = x + (size_t)warp * HH;
    float acc[NE];
#pragma unroll
    for (int e = 0; e < NE; e++) acc[e] = 0.f;
    for (int k = lane; k < HH; k += 32) {
        float xv = xt[k];
#pragma unroll
        for (int e = 0; e < NE; e++) acc[e] += xv * Wgate[e * HH + k];
    }
#pragma unroll
    for (int off = 16; off > 0; off >>= 1) {
#pragma unroll
        for (int e = 0; e < NE; e++) acc[e] += __shfl_xor_sync(0xffffffffu, acc[e], off);
    }
    if (lane == 0) {
        int i0 = 0; float l0 = acc[0];
#pragma unroll
        for (int e = 1; e < NE; e++) if (acc[e] > l0) { l0 = acc[e]; i0 = e; }
        int i1 = -1; float l1 = -INFINITY;
#pragma unroll
        for (int e = 0; e < NE; e++) if (e != i0 && acc[e] > l1) { l1 = acc[e]; i1 = e; }
        float w0 = 1.f / (1.f + expf(l1 - l0));
        float w1 = 1.f - w0;
        int p0 = atomicAdd(&g_cnt[i0], 1);
        g_tok[i0 * TT + p0] = warp; g_kid[i0 * TT + p0] = 0; g_wgt[i0 * TT + p0] = w0;
        int p1 = atomicAdd(&g_cnt[i1], 1);
        g_tok[i1 * TT + p1] = warp; g_kid[i1 * TT + p1] = 1; g_wgt[i1 * TT + p1] = w1;
    }
}

// gather x rows into per-expert compact fp16 layout (one warp per slot)
__global__ void gather_kernel(const float* __restrict__ x) {
    int slot = blockIdx.x * 8 + (threadIdx.x >> 5);
    int lane = threadIdx.x & 31;
    int e = slot / TT, r = slot % TT;
    if (r >= g_cnt[e]) return;
    int t = g_tok[e * TT + r];
    const float4* src = (const float4*)(x + (size_t)t * HH);
    __half2* dst = (__half2*)(g_xh + (size_t)slot * HH);
#pragma unroll
    for (int q = 0; q < HH / 128; q++) {
        float4 v = src[lane + q * 32];
        dst[(lane + q * 32) * 2 + 0] = __floats2half2_rn(v.x, v.y);
        dst[(lane + q * 32) * 2 + 1] = __floats2half2_rn(v.z, v.w);
    }
}

// ---------------- gate+up: fp16 mma.m16n8k16, ldmatrix, cp.async pipeline ----------------
// Block 128x64, 256 threads, warps 2x4, warp tile 64x16 (per operand).
__global__ __launch_bounds__(256) void gateup_hmma(const float* __restrict__ Wg,
                                                   const float* __restrict__ Wu) {
    const int STG = BM * ASTR + 2 * BN * ASTR;  // halves per stage (A, Bg, Bu)
    __shared__ __half sh[2 * STG];

    int e = blockIdx.z, n = g_cnt[e];
    int m0 = blockIdx.x * BM;
    if (m0 >= n) return;
    int n0 = blockIdx.y * BN;

    int tid = threadIdx.x, lane = tid & 31, wid = tid >> 5;
    int wm = wid >> 2, wn = wid & 3;
    uint32_t sb = smem_u32(sh);

    const __half* xab = g_xh + (size_t)e * TT * HH;
    const float*  wgb = Wg + (size_t)e * FF * HH;
    const float*  wub = Wu + (size_t)e * FF * HH;

    // A cp.async mapping: 512 16B chunks, 2 per thread
    const __half* asrc[2]; uint32_t adst[2];
#pragma unroll
    for (int i = 0; i < 2; i++) {
        int ch = tid + i * 256, r = ch >> 2, c = ch & 3;
        int rc = m0 + r; if (rc >= n) rc = n - 1;
        asrc[i] = xab + (size_t)rc * HH + c * 8;
        adst[i] = sb + (r * ASTR + c * 8) * 2;
    }
    // B: row tid>>2 (0..63), chunk tid&3 (8 floats)
    int brow = tid >> 2, bc = tid & 3;
    const float* gsrc = wgb + (size_t)(n0 + brow) * HH + bc * 8;
    const float* usrc = wub + (size_t)(n0 + brow) * HH + bc * 8;
    __half* bgst = sh + BM * ASTR + brow * ASTR + bc * 8;
    __half* bust = bgst + BN * ASTR;

    // fragment base addresses (stage 0)
    int seg = lane >> 3, li = lane & 7;
    uint32_t aA[4], aG, aU;
#pragma unroll
    for (int i = 0; i < 4; i++) {
        int row = wm * 64 + i * 16 + li + (seg & 1) * 8;
        aA[i] = sb + (row * ASTR + (seg >> 1) * 8) * 2;
    }
    {
        int row = wn * 16 + li + (seg >> 1) * 8;
        aG = sb + (BM * ASTR + row * ASTR + (seg & 1) * 8) * 2;
        aU = aG + BN * ASTR * 2;
    }

    float accg[4][2][4] = {}, accu[4][2][4] = {};

    // prologue: stage 0
    cp16(adst[0], asrc[0]); cp16(adst[1], asrc[1]); CP_COMMIT();
    float4 vg0 = *(const float4*)gsrc, vg1 = *(const float4*)(gsrc + 4);
    float4 vu0 = *(const float4*)usrc, vu1 = *(const float4*)(usrc + 4);
    sts8(bgst, vg0, vg1); sts8(bust, vu0, vu1);
    CP_WAIT();
    __syncthreads();

    const int KT = HH / BKH;  // 32
    for (int kt = 0; kt < KT; kt++) {
        int cur = kt & 1;
        uint32_t so = (uint32_t)(cur * STG * 2);
        bool more = (kt + 1 < KT);
        if (more) {
            int k0 = (kt + 1) * BKH;
            uint32_t po = (uint32_t)((cur ^ 1) * STG * 2);
            cp16(adst[0] + po, asrc[0] + k0);
            cp16(adst[1] + po, asrc[1] + k0);
            CP_COMMIT();
            vg0 = *(const float4*)(gsrc + k0); vg1 = *(const float4*)(gsrc + k0 + 4);
            vu0 = *(const float4*)(usrc + k0); vu1 = *(const float4*)(usrc + k0 + 4);
        }
#pragma unroll
        for (int ks = 0; ks < 2; ks++) {
            uint32_t af[4][4], bg[4], bu[4];
            ldsm4(bg, aG + so + ks * 32);
            ldsm4(bu, aU + so + ks * 32);
#pragma unroll
            for (int i = 0; i < 4; i++) ldsm4(af[i], aA[i] + so + ks * 32);
#pragma unroll
            for (int i = 0; i < 4; i++)
#pragma unroll
                for (int j = 0; j < 2; j++) {
                    mma16816(accg[i][j], af[i], &bg[j * 2]);
                    mma16816(accu[i][j], af[i], &bu[j * 2]);
                }
        }
        if (more) {
            __half* bo = bgst + (cur ^ 1) * STG;
            sts8(bo, vg0, vg1);
            sts8(bo + BN * ASTR, vu0, vu1);
            CP_WAIT();
        }
        __syncthreads();
    }

    // epilogue: SwiGLU -> fp16 g_hh
#pragma unroll
    for (int i = 0; i < 4; i++) {
        int row0 = m0 + wm * 64 + i * 16 + (lane >> 2);
        int row1 = row0 + 8;
#pragma unroll
        for (int j = 0; j < 2; j++) {
            int col = n0 + wn * 16 + j * 8 + (lane & 3) * 2;
            if (row0 < n) {
                float a0 = accg[i][j][0], a1 = accg[i][j][1];
                float h0 = (a0 / (1.f + expf(-a0))) * accu[i][j][0];
                float h1 = (a1 / (1.f + expf(-a1))) * accu[i][j][1];
                *(__half2*)(g_hh + ((size_t)e * TT + row0) * FF + col) = __floats2half2_rn(h0, h1);
            }
            if (row1 < n) {
                float a2 = accg[i][j][2], a3 = accg[i][j][3];
                float h2 = (a2 / (1.f + expf(-a2))) * accu[i][j][2];
                float h3 = (a3 / (1.f + expf(-a3))) * accu[i][j][3];
                *(__half2*)(g_hh + ((size_t)e * TT + row1) * FF + col) = __floats2half2_rn(h2, h3);
            }
        }
    }
}

// ---------------- down: fp16 mma, K=FF ----------------
__global__ __launch_bounds__(256) void down_hmma(const float* __restrict__ Wd) {
    const int STG = BM * ASTR + BN * ASTR;  // A + B
    __shared__ __half sh[2 * STG];

    int e = blockIdx.z, n = g_cnt[e];
    int m0 = blockIdx.x * BM;
    if (m0 >= n) return;
    int n0 = blockIdx.y * BN;

    int tid = threadIdx.x, lane = tid & 31, wid = tid >> 5;
    int wm = wid >> 2, wn = wid & 3;
    uint32_t sb = smem_u32(sh);

    const __half* hab = g_hh + (size_t)e * TT * FF;
    const float*  wdb = Wd + (size_t)e * HH * FF;

    const __half* asrc[2]; uint32_t adst[2];
#pragma unroll
    for (int i = 0; i < 2; i++) {
        int ch = tid + i * 256, r = ch >> 2, c = ch & 3;
        int rc = m0 + r; if (rc >= n) rc = n - 1;
        asrc[i] = hab + (size_t)rc * FF + c * 8;
        adst[i] = sb + (r * ASTR + c * 8) * 2;
    }
    int brow = tid >> 2, bc = tid & 3;
    const float* bsrc = wdb + (size_t)(n0 + brow) * FF + bc * 8;
    __half* bst = sh + BM * ASTR + brow * ASTR + bc * 8;

    int seg = lane >> 3, li = lane & 7;
    uint32_t aA[4], aB;
#pragma unroll
    for (int i = 0; i < 4; i++) {
        int row = wm * 64 + i * 16 + li + (seg & 1) * 8;
        aA[i] = sb + (row * ASTR + (seg >> 1) * 8) * 2;
    }
    {
        int row = wn * 16 + li + (seg >> 1) * 8;
        aB = sb + (BM * ASTR + row * ASTR + (seg & 1) * 8) * 2;
    }

    float acc[4][2][4] = {};

    cp16(adst[0], asrc[0]); cp16(adst[1], asrc[1]); CP_COMMIT();
    float4 vb0 = *(const float4*)bsrc, vb1 = *(const float4*)(bsrc + 4);
    sts8(bst, vb0, vb1);
    CP_WAIT();
    __syncthreads();

    const int KT = FF / BKH;  // 88
    for (int kt = 0; kt < KT; kt++) {
        int cur = kt & 1;
        uint32_t so = (uint32_t)(cur * STG * 2);
        bool more = (kt + 1 < KT);
        if (more) {
            int k0 = (kt + 1) * BKH;
            uint32_t po = (uint32_t)((cur ^ 1) * STG * 2);
            cp16(adst[0] + po, asrc[0] + k0);
            cp16(adst[1] + po, asrc[1] + k0);
            CP_COMMIT();
            vb0 = *(const float4*)(bsrc + k0); vb1 = *(const float4*)(bsrc + k0 + 4);
        }
#pragma unroll
        for (int ks = 0; ks < 2; ks++) {
            uint32_t af[4][4], bf[4];
            ldsm4(bf, aB + so + ks * 32);
#pragma unroll
            for (int i = 0; i < 4; i++) ldsm4(af[i], aA[i] + so + ks * 32);
#pragma unroll
            for (int i = 0; i < 4; i++)
#pragma unroll
                for (int j = 0; j < 2; j++) mma16816(acc[i][j], af[i], &bf[j * 2]);
        }
        if (more) {
            sts8(bst + (cur ^ 1) * STG, vb0, vb1);
            CP_WAIT();
        }
        __syncthreads();
    }

    // epilogue: scale by combine weight, scatter fp32
#pragma unroll
    for (int i = 0; i < 4; i++) {
        int row0 = m0 + wm * 64 + i * 16 + (lane >> 2);
        int row1 = row0 + 8;
        bool v0 = row0 < n, v1 = row1 < n;
        int t0 = 0, kk0 = 0; float w0 = 0.f;
        if (v0) { t0 = g_tok[e * TT + row0]; kk0 = g_kid[e * TT + row0]; w0 = g_wgt[e * TT + row0]; }
        int t1 = 0, kk1 = 0; float w1 = 0.f;
        if (v1) { t1 = g_tok[e * TT + row1]; kk1 = g_kid[e * TT + row1]; w1 = g_wgt[e * TT + row1]; }
#pragma unroll
        for (int j = 0; j < 2; j++) {
            int col = n0 + wn * 16 + j * 8 + (lane & 3) * 2;
            if (v0) {
                float2 o; o.x = acc[i][j][0] * w0; o.y = acc[i][j][1] * w0;
                *(float2*)(g_yc + ((size_t)(t0 * 2 + kk0)) * HH + col) = o;
            }
            if (v1) {
                float2 o; o.x = acc[i][j][2] * w1; o.y = acc[i][j][3] * w1;
                *(float2*)(g_yc + ((size_t)(t1 * 2 + kk1)) * HH + col) = o;
            }
        }
    }
}

__global__ void combine_kernel(float* __restrict__ out) {
    int i = blockIdx.x * blockDim.x + threadIdx.x;
    int t  = i / (HH / 4);
    int h4 = (i % (HH / 4)) * 4;
    float4 a = *(const float4*)(g_yc + ((size_t)t * 2) * HH + h4);
    float4 b = *(const float4*)(g_yc + ((size_t)(t * 2 + 1)) * HH + h4);
    float4 o;
    o.x = a.x + b.x; o.y = a.y + b.y; o.z = a.z + b.z; o.w = a.w + b.w;
    *(float4*)(out + (size_t)t * HH + h4) = o;
}

// ---------------- launch ----------------
extern "C" void kernel_launch(void* const* d_in, const int* in_sizes, int n_in,
                              void* d_out, int out_size) {
    const float* x     = (const float*)d_in[0];
    const float* Wgate = (const float*)d_in[1];
    const float* Wg    = (const float*)d_in[2];
    const float* Wu    = (const float*)d_in[3];
    const float* Wd    = (const float*)d_in[4];
    float* out = (float*)d_out;

    zero_kernel<<<1, 32>>>();
    router_kernel<<<TT / 8, 256>>>(x, Wgate);
    gather_kernel<<<NE * TT / 8, 256>>>(x);
    gateup_hmma<<<dim3(TT / 128, FF / 64, NE), 256>>>(Wg, Wu);
    down_hmma<<<dim3(TT / 128, HH / 64, NE), 256>>>(Wd);
    combine_kernel<<<(TT * HH / 4) / 256, 256>>>(out);
}